// round 2
// baseline (speedup 1.0000x reference)
#include <cuda_runtime.h>

// Problem constants (fixed by the reference)
#define NB        2000                  // N_BUSES
#define BATCH     32                    // B
#define NEDGE     6000                  // E per batch
#define TOT_NODES (BATCH * NB)          // 64000
#define TOT_EDGES (BATCH * NEDGE)       // 192000
#define HSLOTS    16384                 // per-batch hash slots (pow2, load 0.37)
#define HMASK     (HSLOTS - 1)

// Static scratch (no allocations allowed)
__device__ unsigned long long g_hash[BATCH * HSLOTS]; // 4 MB: (cell+1)<<32 | edge_id
__device__ float2             g_yv[TOT_NODES];        // YV accumulator (complex)
__device__ double             g_acc[8];               // d1r, d1i, d2, d3, mse

__device__ __forceinline__ unsigned hash_cell(unsigned cell) {
    return (cell * 2654435761u) & HMASK;
}

// ---------------------------------------------------------------- init scratch
__global__ void k_init() {
    int idx    = blockIdx.x * blockDim.x + threadIdx.x;
    int stride = gridDim.x * blockDim.x;
    for (int i = idx; i < BATCH * HSLOTS; i += stride) g_hash[i] = 0ULL;
    for (int i = idx; i < TOT_NODES;      i += stride) g_yv[i]   = make_float2(0.f, 0.f);
    if (idx < 8) g_acc[idx] = 0.0;
}

// ------------------------------------------- pass 1: last-write-wins hash insert
// JAX .at[...].set with duplicate indices: last update (largest e within batch) wins.
__global__ void k_insert(const int* __restrict__ ei) {
    int t = blockIdx.x * blockDim.x + threadIdx.x;
    if (t >= TOT_EDGES) return;
    int b = t / NEDGE;
    int e = t - b * NEDGE;
    int i = ei[t] % NB;              if (i < 0) i += NB;
    int j = ei[TOT_EDGES + t] % NB;  if (j < 0) j += NB;

    unsigned cell = (unsigned)(i * NB + j) + 1u;            // +1 so 0 == empty
    unsigned long long mine = ((unsigned long long)cell << 32) | (unsigned)e;
    unsigned h = hash_cell(cell);
    unsigned long long* tab = g_hash + (size_t)b * HSLOTS;

    while (true) {
        unsigned long long old = atomicCAS(&tab[h], 0ULL, mine);
        if (old == 0ULL) break;                              // claimed empty slot
        if ((unsigned)(old >> 32) == cell) {                 // same cell: max edge wins
            atomicMax(&tab[h], mine);
            break;
        }
        h = (h + 1) & HMASK;                                 // linear probe
    }
}

// -------------------------- pass 2: winning edges scatter adm*V[j] into YV[b,i]
__global__ void k_scatter(const int* __restrict__ ei,
                          const float* __restrict__ ea,
                          const float* __restrict__ outs) {
    int t = blockIdx.x * blockDim.x + threadIdx.x;
    if (t >= TOT_EDGES) return;
    int b = t / NEDGE;
    int e = t - b * NEDGE;
    int i = ei[t] % NB;              if (i < 0) i += NB;
    int j = ei[TOT_EDGES + t] % NB;  if (j < 0) j += NB;

    unsigned cell = (unsigned)(i * NB + j) + 1u;
    unsigned h = hash_cell(cell);
    const unsigned long long* tab = g_hash + (size_t)b * HSLOTS;
    unsigned long long s;
    while (true) {
        s = tab[h];
        if ((unsigned)(s >> 32) == cell) break;
        h = (h + 1) & HMASK;
    }
    if ((unsigned)s != (unsigned)e) return;                  // lost to a later duplicate

    float ar = ea[2 * t], ai = ea[2 * t + 1];                // adm (complex)
    int   nj = b * NB + j;
    float vr = outs[2 * nj], vi = outs[2 * nj + 1];          // Vpred[j]
    float tr = ar * vr - ai * vi;                            // adm * V
    float ti = ar * vi + ai * vr;
    int   ni = b * NB + i;
    atomicAdd(&g_yv[ni].x, tr);
    atomicAdd(&g_yv[ni].y, ti);
}

// ----------------------------- per-node physics + MSE terms, reduced to doubles
__global__ void k_node(const float* __restrict__ x,
                       const float* __restrict__ outs,
                       const float* __restrict__ labels) {
    int idx = blockIdx.x * blockDim.x + threadIdx.x;
    double a0 = 0, a1 = 0, a2 = 0, a3 = 0, a4 = 0;

    if (idx < TOT_NODES) {
        float vr = outs[2 * idx], vi = outs[2 * idx + 1];
        float2 yv = g_yv[idx];
        // Spred = V * conj(YV)
        float spr = vr * yv.x + vi * yv.y;
        float spi = vi * yv.x - vr * yv.y;

        const float* nf = x + 6 * idx;
        float sr = nf[0], si = nf[1], Vm = nf[2];
        float b0 = nf[3], b1 = nf[4], b2 = nf[5];

        float dr = spr - sr;
        float di = spi - si;
        float sinv = 1.f / sqrtf(sr * sr + si * si);         // |1/S| (S never exactly 0)

        // D1 = sinv * ((Spred-S)^2 * b0 + (Re(Spred)-Re(S))^2 * b1)   (complex)
        a0 = (double)(sinv * ((dr * dr - di * di) * b0 + dr * dr * b1));
        a1 = (double)(sinv * (2.f * dr * di * b0));

        float vmag  = sqrtf(vr * vr + vi * vi);
        float vminv = 1.f / Vm;                              // Vm never exactly 0
        a2 = (double)(fabsf(vmag * (b1 + b2) - Vm) * vminv);
        a3 = (double)(fabsf(vi * b2) * vminv);

        float e0 = vr - labels[2 * idx];
        float e1 = vi - labels[2 * idx + 1];
        a4 = (double)(e0 * e0) + (double)(e1 * e1);
    }

    // warp reduce
    #pragma unroll
    for (int o = 16; o > 0; o >>= 1) {
        a0 += __shfl_down_sync(0xFFFFFFFFu, a0, o);
        a1 += __shfl_down_sync(0xFFFFFFFFu, a1, o);
        a2 += __shfl_down_sync(0xFFFFFFFFu, a2, o);
        a3 += __shfl_down_sync(0xFFFFFFFFu, a3, o);
        a4 += __shfl_down_sync(0xFFFFFFFFu, a4, o);
    }

    __shared__ double sm[5][8];                              // 256 thr = 8 warps
    int lane = threadIdx.x & 31, warp = threadIdx.x >> 5;
    if (lane == 0) { sm[0][warp] = a0; sm[1][warp] = a1; sm[2][warp] = a2;
                     sm[3][warp] = a3; sm[4][warp] = a4; }
    __syncthreads();
    if (warp == 0) {
        int nw = blockDim.x >> 5;
        double v0 = (lane < nw) ? sm[0][lane] : 0.0;
        double v1 = (lane < nw) ? sm[1][lane] : 0.0;
        double v2 = (lane < nw) ? sm[2][lane] : 0.0;
        double v3 = (lane < nw) ? sm[3][lane] : 0.0;
        double v4 = (lane < nw) ? sm[4][lane] : 0.0;
        #pragma unroll
        for (int o = 4; o > 0; o >>= 1) {
            v0 += __shfl_down_sync(0xFFFFFFFFu, v0, o);
            v1 += __shfl_down_sync(0xFFFFFFFFu, v1, o);
            v2 += __shfl_down_sync(0xFFFFFFFFu, v2, o);
            v3 += __shfl_down_sync(0xFFFFFFFFu, v3, o);
            v4 += __shfl_down_sync(0xFFFFFFFFu, v4, o);
        }
        if (lane == 0) {
            atomicAdd(&g_acc[0], v0);
            atomicAdd(&g_acc[1], v1);
            atomicAdd(&g_acc[2], v2);
            atomicAdd(&g_acc[3], v3);
            atomicAdd(&g_acc[4], v4);
        }
    }
}

// ------------------------------------------------------------------ finalize
// Output layout: 5 float32 = REAL PARTS of (loss, physics_loss, d1, d2, d3).
// (complex -> float32 cast in numpy takes the real component)
__global__ void k_final(float* __restrict__ out, int nfloats) {
    const double inv = 1.0 / (double)TOT_NODES;
    double d1r = g_acc[0] * inv;
    double d1i = g_acc[1] * inv;
    double d2  = g_acc[2] * inv;
    double d3  = g_acc[3] * inv;
    double mse = g_acc[4] / (double)(TOT_NODES * 2);
    double pr  = d1r + d2 + d3;                              // W1=W2=W3=1 (real part)
    double pi  = d1i;
    double lr  = mse + 0.1 * pr;                             // LMBDA = 0.1
    double li  = 0.1 * pi;
    // First 5 slots: real parts (the confirmed float32 layout).
    // Slots 5..9: imag parts, only written if the buffer is larger (hedge).
    float vals[10] = { (float)lr, (float)pr, (float)d1r, (float)d2, (float)d3,
                       (float)li, (float)pi, (float)d1i, 0.f, 0.f };
    for (int k = 0; k < nfloats && k < 10; k++) out[k] = vals[k];
}

// ------------------------------------------------------------------ launcher
extern "C" void kernel_launch(void* const* d_in, const int* in_sizes, int n_in,
                              void* d_out, int out_size) {
    const float* x      = (const float*)d_in[0];   // (B*2000, 6)
    const float* ea     = (const float*)d_in[1];   // (B*6000, 2)
    const int*   ei     = (const int*)  d_in[2];   // (2, B*6000)
    const float* outs   = (const float*)d_in[3];   // (B*2000, 2)
    const float* labels = (const float*)d_in[4];   // (B*2000, 2)
    (void)in_sizes; (void)n_in;

    int nfloats = out_size < 10 ? out_size : 10;

    k_init   <<<2048, 256>>>();
    k_insert <<<(TOT_EDGES + 255) / 256, 256>>>(ei);
    k_scatter<<<(TOT_EDGES + 255) / 256, 256>>>(ei, ea, outs);
    k_node   <<<(TOT_NODES + 255) / 256, 256>>>(x, outs, labels);
    k_final  <<<1, 1>>>((float*)d_out, nfloats);
}